// round 14
// baseline (speedup 1.0000x reference)
#include <cuda_runtime.h>
#include <math.h>

#define NA     24564          // anchors per batch
#define NAP    24576          // padded to 24*1024
#define NB     32             // batch
#define NCH    93
#define TOPK   200
#define CONF_TH 0.01f
#define IOU_TH  0.45f
#define CANDN  512            // max selected candidates
#define SELTGT 256            // selection target
#define SBINS  8192           // 13-bit digit bins (key bits [63:51])

typedef unsigned long long u64;
typedef unsigned int u32;

// scratch (device globals: no allocation allowed)
__device__ u64    g_keys [NB * NAP];   // mono(conf)<<32 | (~anchor); 0 if invalid
__device__ float4 g_boxes[NB * NAP];
__device__ float  g_cls  [NB * NAP];

// ---------------------------------------------------------------------------
// Kernel 1: decode. 256 threads / 64 anchors; 4 threads cooperate per anchor
// (strided 21-class scans + shuffle merge) so ALL threads work the tail.
// ---------------------------------------------------------------------------
__global__ void __launch_bounds__(256) decode_kernel(const float* __restrict__ y)
{
    extern __shared__ float smF[];        // 64*93 floats
    const int b   = blockIdx.y;
    const int a0  = blockIdx.x * 64;
    const int cnt = min(64, NA - a0);
    const int tid = threadIdx.x;

    const float* base = y + ((size_t)b * NA + a0) * NCH;
    const int nvec = (cnt * NCH) >> 2;
    const float4* b4 = (const float4*)base;
    float4* s4 = (float4*)smF;
    #pragma unroll 2
    for (int i = tid; i < nvec; i += 256) s4[i] = b4[i];
    __syncthreads();

    const int a     = tid >> 2;           // anchor within block
    const int q     = tid & 3;            // sub-thread within anchor
    const bool have = (a < cnt);
    const int  ae   = have ? a : (cnt - 1);     // clamp: keep lanes resident
    const float* r  = smF + ae * NCH;     // stride 93 (odd) -> conflict-free

    // strided local argmax over classes {q, q+4, ...} ∩ [0,81)
    float best = -1e30f; int bi = 1000;
    #pragma unroll
    for (int c = 0; c < 21; c++) {
        const int cc = q + 4 * c;
        if (cc < 81) {
            const float v = r[cc];
            if (v > best) { best = v; bi = cc; }
        }
    }
    // merge across the 4 lanes of this anchor (lower index wins ties)
    #pragma unroll
    for (int off = 1; off < 4; off <<= 1) {
        const float ov = __shfl_xor_sync(0xffffffffu, best, off);
        const int   oi = __shfl_xor_sync(0xffffffffu, bi,   off);
        if (ov > best || (ov == best && oi < bi)) { best = ov; bi = oi; }
    }

    if (q == 0 && have) {
        const float y81 = r[81], y82 = r[82], y83 = r[83], y84 = r[84];
        const float y85 = r[85], y86 = r[86], y87 = r[87], y88 = r[88];
        const float y89 = r[89], y90 = r[90], y91 = r[91], y92 = r[92];

        const float cx = y81 * y89 * y87 + y85;
        const float cy = y82 * y90 * y88 + y86;
        const float w  = expf(y83 * y91) * y87;
        const float h  = expf(y84 * y92) * y88;

        float4 box;
        box.x = (cx - 0.5f * w) * 512.0f;
        box.y = (cy - 0.5f * h) * 512.0f;
        box.z = (cx + 0.5f * w) * 512.0f;
        box.w = (cy + 0.5f * h) * 512.0f;

        const int  anchor = a0 + a;
        const int  idx    = b * NAP + anchor;
        const bool valid  = (bi != 0) && (best > CONF_TH);
        const u32  mono   = __float_as_uint(best) | 0x80000000u;
        g_keys [idx] = valid ? (((u64)mono << 32) |
                                (u64)(0xFFFFFFFFu - (u32)anchor)) : 0ull;
        g_boxes[idx] = box;
        g_cls  [idx] = (float)bi;
    }
}

// ---------------------------------------------------------------------------
__device__ __forceinline__ bool iou_gt(const float4 w, const float4 ab)
{
    const float ix1 = fmaxf(w.x, ab.x);
    const float iy1 = fmaxf(w.y, ab.y);
    const float ix2 = fminf(w.z, ab.z);
    const float iy2 = fminf(w.w, ab.w);
    const float iw  = fmaxf(__fsub_rn(ix2, ix1), 0.0f);
    const float ih  = fmaxf(__fsub_rn(iy2, iy1), 0.0f);
    const float inter = __fmul_rn(iw, ih);
    const float a1  = __fmul_rn(__fsub_rn(w.z, w.x), __fsub_rn(w.w, w.y));
    const float a2  = __fmul_rn(__fsub_rn(ab.z, ab.x), __fsub_rn(ab.w, ab.y));
    const float uni = __fsub_rn(__fadd_rn(a1, a2), inter);
    return (uni > 0.0f) && (__fdiv_rn(inter, uni) > IOU_TH);
}

// ---------------------------------------------------------------------------
// Kernel 2: fused select + sort + walk. One CTA (1024 thr) per batch.
// (unchanged from round 13 — measured 35us)
// ---------------------------------------------------------------------------
__global__ void __launch_bounds__(1024, 1) nms_kernel(float* __restrict__ out)
{
    __shared__ u32 wsum[32];
    __shared__ u32 woff[32];
    __shared__ u64 sh_pv;
    __shared__ u32 sh_cnt;
    __shared__ u32 wv_sup [2][32];
    __shared__ u32 wv_mask[2][32];

    extern __shared__ u64 smW[];
    u32*    hist = (u32*)smW;                 // 8192 bins  (32768 B)
    u64*    cand = (u64*)(hist + SBINS);      // 512 keys   (4096 B)
    float4* cbox = (float4*)(cand + CANDN);   // 512 boxes  (8192 B)
    float*  ccls = (float*)(cbox + CANDN);    // 512 cls    (2048 B)
    float4* abox = (float4*)(ccls + CANDN);   // 200 accepted (3200 B)

    const int b    = blockIdx.x;
    const int tid  = threadIdx.x;
    const int lane = tid & 31;
    const int wid  = tid >> 5;
    const u64* gk  = g_keys + (size_t)b * NAP;
    const u32* gkh = (const u32*)gk;          // high words at odd indices

    for (int j = tid; j < TOPK * 6; j += 1024)
        out[b * TOPK * 6 + j] = 0.0f;

    #pragma unroll
    for (int i = 0; i < SBINS / 1024; i++) hist[tid + i * 1024] = 0u;
    if (tid < CANDN) cand[tid] = 0ull;
    if (tid == 0) { sh_pv = 1ull; sh_cnt = 0u; }
    __syncthreads();

    // ---- (a) histogram over key HIGH words (digit = bits[63:51]) ----
    #pragma unroll
    for (int it = 0; it < NAP / 1024; it++) {
        const u32 kh = gkh[2 * (tid + it * 1024) + 1];
        if (kh) atomicAdd(&hist[kh >> 19], 1u);
    }
    __syncthreads();

    // per-thread segment sum (8 consecutive bins)
    u32 s = 0;
    #pragma unroll
    for (int i = 0; i < 8; i++) s += hist[tid * 8 + i];

    // warp inclusive suffix sum over lanes
    u32 v = s;
    #pragma unroll
    for (int off = 1; off < 32; off <<= 1) {
        const u32 o = __shfl_down_sync(0xffffffffu, v, off);
        if (lane + off < 32) v += o;
    }
    if (lane == 0) wsum[wid] = v;
    __syncthreads();
    if (wid == 0) {
        const u32 wv_ = wsum[lane];
        u32 vv = wv_;
        #pragma unroll
        for (int off = 1; off < 32; off <<= 1) {
            const u32 o = __shfl_down_sync(0xffffffffu, vv, off);
            if (lane + off < 32) vv += o;
        }
        woff[lane] = vv - wv_;                // suffix of later warps
    }
    __syncthreads();

    const u32 St  = v + woff[wid];            // keys in bins >= tid*8
    const u32 St1 = St - s;                   // keys in bins >= (tid+1)*8
    if (St >= SELTGT && St1 < SELTGT) {       // unique crossing segment
        u32 c = St1;
        int d = tid * 8; u32 h = 0;
        for (int i = 7; i >= 0; i--) {
            h = hist[tid * 8 + i];
            if (c + h >= SELTGT) { d = tid * 8 + i; break; }
            c += h;
        }
        u64 pv;
        if (c + h <= CANDN) pv = ((u64)(u32)d) << 51;
        else pv = (d == SBINS - 1) ? ~0ull : (((u64)(u32)(d + 1)) << 51);
        sh_pv = pv;
    }
    __syncthreads();
    const u64 pv = sh_pv;

    // ---- (b) compaction into SMEM cand ----
    #pragma unroll
    for (int it = 0; it < NAP / 1024; it++) {
        const u64 k = gk[tid + it * 1024];
        const bool sel = (k >= pv);
        const u32 bal = __ballot_sync(0xffffffffu, sel);
        if (bal) {
            const int ldr = __ffs(bal) - 1;
            u32 base = 0;
            if (lane == ldr) base = atomicAdd(&sh_cnt, (u32)__popc(bal));
            base = __shfl_sync(0xffffffffu, base, ldr);
            const u32 slot = base + (u32)__popc(bal & ((1u << lane) - 1u));
            if (sel && slot < CANDN) cand[slot] = k;
        }
    }
    __syncthreads();
    const int cnt = min((int)sh_cnt, CANDN);

    // ---- (c) hybrid bitonic sort of CANDN keys, descending; zeros pad ----
    {
        u64 vv = (tid < CANDN) ? cand[tid] : 0ull;
        #pragma unroll
        for (int k = 2; k <= 32; k <<= 1) {
            const bool desc = ((tid & k) == 0);
            #pragma unroll
            for (int j = k >> 1; j >= 1; j >>= 1) {
                const u64 o = __shfl_xor_sync(0xffffffffu, vv, j);
                const bool lower = ((tid & j) == 0);
                vv = ((desc == lower) ? (vv > o) : (vv < o)) ? vv : o;
            }
        }
        if (tid < CANDN) cand[tid] = vv;

        for (int k = 64; k <= CANDN; k <<= 1) {
            for (int j = k >> 1; j >= 32; j >>= 1) {
                __syncthreads();
                if (tid < CANDN / 2) {
                    const int t = ((tid & ~(j - 1)) << 1) | (tid & (j - 1));
                    const int p = t | j;
                    const u64 A = cand[t];
                    const u64 B = cand[p];
                    const bool desc = ((t & k) == 0);
                    if (desc ? (A < B) : (A > B)) { cand[t] = B; cand[p] = A; }
                }
            }
            __syncthreads();
            vv = (tid < CANDN) ? cand[tid] : 0ull;
            const bool desc = ((tid & k) == 0);
            #pragma unroll
            for (int j = 16; j >= 1; j >>= 1) {
                const u64 o = __shfl_xor_sync(0xffffffffu, vv, j);
                const bool lower = ((tid & j) == 0);
                vv = ((desc == lower) ? (vv > o) : (vv < o)) ? vv : o;
            }
            if (tid < CANDN) cand[tid] = vv;
        }
        __syncthreads();
    }

    // ---- (d) gather candidate boxes/classes into SMEM ----
    if (tid < cnt) {
        const u64 k  = cand[tid];
        const int a_ = (int)(0xFFFFFFFFu - (u32)k);
        cbox[tid] = g_boxes[(size_t)b * NAP + a_];
        ccls[tid] = g_cls  [(size_t)b * NAP + a_];
    }
    __syncthreads();

    // ---- single-barrier wave walk ----
    int A = 0;                 // committed accepted (visible pre-barrier)
    int T = 0;                 // total accepted so far
    int pbase = 0;             // previous wave base
    u32 pmask = 0;             // previous wave accept mask

    for (int base = 0; base < cnt && T < TOPK; base += 32) {
        const int  c     = base + wid;
        const bool haveC = (c < cnt);
        const int  pb    = (base >> 5) & 1;

        float4 w = make_float4(0.f, 0.f, 0.f, 0.f);
        if (haveC) w = cbox[c];

        bool sA = false;
        if (haveC) {
            for (int a = lane; a < A; a += 32)
                if (iou_gt(w, abox[a])) sA = true;
            if ((pmask >> lane) & 1u)
                if (iou_gt(w, cbox[pbase + lane])) sA = true;
        }
        const bool supA = (__ballot_sync(0xffffffffu, sA) != 0u);

        bool ov = false;
        if (haveC && lane < wid)
            ov = iou_gt(w, cbox[base + lane]);
        const u32 m = __ballot_sync(0xffffffffu, ov);

        if (lane == 0) {
            wv_sup [pb][wid] = (haveC && !supA) ? 0u : 1u;
            wv_mask[pb][wid] = m;
        }
        __syncthreads();

        // fast path: no suppression + no intra-wave overlap (dominant case)
        const u32 sup_l   = wv_sup [pb][lane];
        const u32 mask_l  = wv_mask[pb][lane];
        const u32 supmask = __ballot_sync(0xffffffffu, sup_l != 0u);
        const u32 anyov   = __ballot_sync(0xffffffffu, mask_l != 0u);

        u32 alive;
        int tot;
        if ((supmask | anyov) == 0u) {
            const int take = min(32, TOPK - T);
            alive = (take >= 32) ? 0xffffffffu : ((1u << take) - 1u);
            tot = T + take;
        } else {
            alive = 0u;
            tot = T;
            #pragma unroll
            for (int i = 0; i < 32; i++) {
                if (tot >= TOPK) break;
                if (!wv_sup[pb][i] && ((wv_mask[pb][i] & alive) == 0u)) {
                    alive |= (1u << i);
                    tot++;
                }
            }
        }

        if ((alive >> wid) & 1u) {
            const int slot = T + __popc(alive & ((1u << wid) - 1u));
            if (lane == 0) {
                abox[slot] = w;
                const u64 k = cand[c];
                float* o = out + ((size_t)b * TOPK + slot) * 6;
                o[0] = ccls[c];
                o[1] = __uint_as_float((u32)(k >> 32) ^ 0x80000000u);
                o[2] = w.x; o[3] = w.y; o[4] = w.z; o[5] = w.w;
            }
        }
        A = T;
        pbase = base;
        pmask = alive;
        T = tot;
    }
    __syncthreads();           // all abox writes visible for fallback

    if (tid >= 32) return;     // fallback: warp 0 only (rare)
    int acc = T;

    const float4* gb = g_boxes + (size_t)b * NAP;
    const float*  gc = g_cls   + (size_t)b * NAP;

    if (acc < TOPK) {
        u64 last = pv;
        while (acc < TOPK) {
            u64 best = 0ull;
            for (int j = lane; j < NAP; j += 32) {
                const u64 k = gk[j];
                if (k < last && k > best) best = k;
            }
            const u32 hi = (u32)(best >> 32);
            const u32 mh = __reduce_max_sync(0xffffffffu, hi);
            const u32 lo = (hi == mh) ? (u32)best : 0u;
            const u32 ml = __reduce_max_sync(0xffffffffu, lo);
            if (mh == 0u) break;
            const u64 wkey = ((u64)mh << 32) | (u64)ml;
            const int a_   = (int)(0xFFFFFFFFu - ml);

            float4 w;
            if (lane == 0) w = __ldg(&gb[a_]);
            w.x = __shfl_sync(0xffffffffu, w.x, 0);
            w.y = __shfl_sync(0xffffffffu, w.y, 0);
            w.z = __shfl_sync(0xffffffffu, w.z, 0);
            w.w = __shfl_sync(0xffffffffu, w.w, 0);

            bool sup = false;
            for (int a = lane; a < acc; a += 32)
                if (iou_gt(w, abox[a])) sup = true;
            sup = (__ballot_sync(0xffffffffu, sup) != 0u);

            if (!sup) {
                if (lane == 0) {
                    abox[acc] = w;
                    float* o = out + ((size_t)b * TOPK + acc) * 6;
                    o[0] = __ldg(&gc[a_]);
                    o[1] = __uint_as_float(mh ^ 0x80000000u);
                    o[2] = w.x; o[3] = w.y; o[4] = w.z; o[5] = w.w;
                }
                acc++;
            }
            last = wkey;
            __syncwarp();
        }
    }
}

// ---------------------------------------------------------------------------
extern "C" void kernel_launch(void* const* d_in, const int* in_sizes, int n_in,
                              void* d_out, int out_size)
{
    const float* y   = (const float*)d_in[0];
    float*       out = (float*)d_out;

    const int dec_smem = 64 * NCH * 4;    // 23808 B
    cudaFuncSetAttribute(decode_kernel,
                         cudaFuncAttributeMaxDynamicSharedMemorySize, dec_smem);
    dim3 dgrid((NA + 63) / 64, NB);
    decode_kernel<<<dgrid, 256, dec_smem>>>(y);

    const int nms_smem = SBINS * 4 + CANDN * 8 + CANDN * 16 + CANDN * 4
                       + TOPK * 16;       // 50304 B
    cudaFuncSetAttribute(nms_kernel,
                         cudaFuncAttributeMaxDynamicSharedMemorySize, nms_smem);
    nms_kernel<<<NB, 1024, nms_smem>>>(out);
}

// round 15
// speedup vs baseline: 1.0719x; 1.0719x over previous
#include <cuda_runtime.h>
#include <math.h>

#define NA     24564          // anchors per batch
#define NAP    24576          // padded to 24*1024
#define NB     32             // batch
#define NCH    93
#define TOPK   200
#define CONF_TH 0.01f
#define IOU_TH  0.45f
#define CANDN  512            // max selected candidates
#define SELTGT 256            // selection target
#define SBINS  8192           // 13-bit digit bins (key bits [63:51])

typedef unsigned long long u64;
typedef unsigned int u32;

// scratch (device globals: no allocation allowed)
__device__ u64    g_keys [NB * NAP];   // mono(conf)<<32 | (~anchor); 0 if invalid
__device__ float4 g_boxes[NB * NAP];
__device__ float  g_cls  [NB * NAP];

// ---------------------------------------------------------------------------
// Kernel 1: decode. 256 threads / 64 anchors (round-13 version, measured 55us)
// ---------------------------------------------------------------------------
__global__ void __launch_bounds__(256) decode_kernel(const float* __restrict__ y)
{
    extern __shared__ float smF[];        // 64*93 floats
    const int b   = blockIdx.y;
    const int a0  = blockIdx.x * 64;
    const int cnt = min(64, NA - a0);
    const int tid = threadIdx.x;

    const float* base = y + ((size_t)b * NA + a0) * NCH;
    const int nvec = (cnt * NCH) >> 2;
    const float4* b4 = (const float4*)base;
    float4* s4 = (float4*)smF;
    #pragma unroll 2
    for (int i = tid; i < nvec; i += 256) s4[i] = b4[i];
    __syncthreads();

    if (tid >= cnt) return;
    const float* r = smF + tid * NCH;     // stride 93 (odd) -> conflict-free

    float best = r[0]; int bi = 0;
    #pragma unroll
    for (int c = 1; c < 81; c++) {
        const float v = r[c];
        if (v > best) { best = v; bi = c; }   // first-max => lowest index
    }

    const float y81 = r[81], y82 = r[82], y83 = r[83], y84 = r[84];
    const float y85 = r[85], y86 = r[86], y87 = r[87], y88 = r[88];
    const float y89 = r[89], y90 = r[90], y91 = r[91], y92 = r[92];

    const float cx = y81 * y89 * y87 + y85;
    const float cy = y82 * y90 * y88 + y86;
    const float w  = expf(y83 * y91) * y87;
    const float h  = expf(y84 * y92) * y88;

    float4 box;
    box.x = (cx - 0.5f * w) * 512.0f;
    box.y = (cy - 0.5f * h) * 512.0f;
    box.z = (cx + 0.5f * w) * 512.0f;
    box.w = (cy + 0.5f * h) * 512.0f;

    const int  anchor = a0 + tid;
    const int  idx    = b * NAP + anchor;
    const bool valid  = (bi != 0) && (best > CONF_TH);
    const u32  mono   = __float_as_uint(best) | 0x80000000u;
    g_keys [idx] = valid ? (((u64)mono << 32) | (u64)(0xFFFFFFFFu - (u32)anchor))
                         : 0ull;
    g_boxes[idx] = box;
    g_cls  [idx] = (float)bi;
}

// ---------------------------------------------------------------------------
__device__ __forceinline__ bool iou_gt(const float4 w, const float4 ab)
{
    const float ix1 = fmaxf(w.x, ab.x);
    const float iy1 = fmaxf(w.y, ab.y);
    const float ix2 = fminf(w.z, ab.z);
    const float iy2 = fminf(w.w, ab.w);
    const float iw  = fmaxf(__fsub_rn(ix2, ix1), 0.0f);
    const float ih  = fmaxf(__fsub_rn(iy2, iy1), 0.0f);
    const float inter = __fmul_rn(iw, ih);
    const float a1  = __fmul_rn(__fsub_rn(w.z, w.x), __fsub_rn(w.w, w.y));
    const float a2  = __fmul_rn(__fsub_rn(ab.z, ab.x), __fsub_rn(ab.w, ab.y));
    const float uni = __fsub_rn(__fadd_rn(a1, a2), inter);
    return (uni > 0.0f) && (__fdiv_rn(inter, uni) > IOU_TH);
}

// ---------------------------------------------------------------------------
// Kernel 2: fused select + sort + walk. One CTA (1024 thr) per batch.
// Round-13 logic; histogram & compaction passes prefetch 8 keys/batch into
// registers before consuming (MLP 8 instead of ~1) to hide L2 latency.
// ---------------------------------------------------------------------------
__global__ void __launch_bounds__(1024, 1) nms_kernel(float* __restrict__ out)
{
    __shared__ u32 wsum[32];
    __shared__ u32 woff[32];
    __shared__ u64 sh_pv;
    __shared__ u32 sh_cnt;
    __shared__ u32 wv_sup [2][32];
    __shared__ u32 wv_mask[2][32];

    extern __shared__ u64 smW[];
    u32*    hist = (u32*)smW;                 // 8192 bins  (32768 B)
    u64*    cand = (u64*)(hist + SBINS);      // 512 keys   (4096 B)
    float4* cbox = (float4*)(cand + CANDN);   // 512 boxes  (8192 B)
    float*  ccls = (float*)(cbox + CANDN);    // 512 cls    (2048 B)
    float4* abox = (float4*)(ccls + CANDN);   // 200 accepted (3200 B)

    const int b    = blockIdx.x;
    const int tid  = threadIdx.x;
    const int lane = tid & 31;
    const int wid  = tid >> 5;
    const u64* gk  = g_keys + (size_t)b * NAP;
    const u32* gkh = (const u32*)gk;          // high words at odd indices

    for (int j = tid; j < TOPK * 6; j += 1024)
        out[b * TOPK * 6 + j] = 0.0f;

    #pragma unroll
    for (int i = 0; i < SBINS / 1024; i++) hist[tid + i * 1024] = 0u;
    if (tid < CANDN) cand[tid] = 0ull;
    if (tid == 0) { sh_pv = 1ull; sh_cnt = 0u; }
    __syncthreads();

    // ---- (a) histogram over key HIGH words; prefetch 8/batch ----
    #pragma unroll
    for (int bt = 0; bt < 3; bt++) {
        u32 kh[8];
        #pragma unroll
        for (int i = 0; i < 8; i++)
            kh[i] = __ldg(&gkh[2 * (tid + (bt * 8 + i) * 1024) + 1]);
        #pragma unroll
        for (int i = 0; i < 8; i++)
            if (kh[i]) atomicAdd(&hist[kh[i] >> 19], 1u);
    }
    __syncthreads();

    // per-thread segment sum (8 consecutive bins)
    u32 s = 0;
    #pragma unroll
    for (int i = 0; i < 8; i++) s += hist[tid * 8 + i];

    // warp inclusive suffix sum over lanes
    u32 v = s;
    #pragma unroll
    for (int off = 1; off < 32; off <<= 1) {
        const u32 o = __shfl_down_sync(0xffffffffu, v, off);
        if (lane + off < 32) v += o;
    }
    if (lane == 0) wsum[wid] = v;
    __syncthreads();
    if (wid == 0) {
        const u32 wv_ = wsum[lane];
        u32 vv = wv_;
        #pragma unroll
        for (int off = 1; off < 32; off <<= 1) {
            const u32 o = __shfl_down_sync(0xffffffffu, vv, off);
            if (lane + off < 32) vv += o;
        }
        woff[lane] = vv - wv_;                // suffix of later warps
    }
    __syncthreads();

    const u32 St  = v + woff[wid];            // keys in bins >= tid*8
    const u32 St1 = St - s;                   // keys in bins >= (tid+1)*8
    if (St >= SELTGT && St1 < SELTGT) {       // unique crossing segment
        u32 c = St1;
        int d = tid * 8; u32 h = 0;
        for (int i = 7; i >= 0; i--) {
            h = hist[tid * 8 + i];
            if (c + h >= SELTGT) { d = tid * 8 + i; break; }
            c += h;
        }
        u64 pv;
        if (c + h <= CANDN) pv = ((u64)(u32)d) << 51;
        else pv = (d == SBINS - 1) ? ~0ull : (((u64)(u32)(d + 1)) << 51);
        sh_pv = pv;
    }
    __syncthreads();
    const u64 pv = sh_pv;

    // ---- (b) compaction into SMEM cand; prefetch 8/batch ----
    #pragma unroll
    for (int bt = 0; bt < 3; bt++) {
        u64 kk[8];
        #pragma unroll
        for (int i = 0; i < 8; i++)
            kk[i] = __ldg(&gk[tid + (bt * 8 + i) * 1024]);
        #pragma unroll
        for (int i = 0; i < 8; i++) {
            const u64 k = kk[i];
            const bool sel = (k >= pv);
            const u32 bal = __ballot_sync(0xffffffffu, sel);
            if (bal) {
                const int ldr = __ffs(bal) - 1;
                u32 base = 0;
                if (lane == ldr) base = atomicAdd(&sh_cnt, (u32)__popc(bal));
                base = __shfl_sync(0xffffffffu, base, ldr);
                const u32 slot = base + (u32)__popc(bal & ((1u << lane) - 1u));
                if (sel && slot < CANDN) cand[slot] = k;
            }
        }
    }
    __syncthreads();
    const int cnt = min((int)sh_cnt, CANDN);

    // ---- (c) hybrid bitonic sort of CANDN keys, descending; zeros pad ----
    {
        u64 vv = (tid < CANDN) ? cand[tid] : 0ull;
        #pragma unroll
        for (int k = 2; k <= 32; k <<= 1) {
            const bool desc = ((tid & k) == 0);
            #pragma unroll
            for (int j = k >> 1; j >= 1; j >>= 1) {
                const u64 o = __shfl_xor_sync(0xffffffffu, vv, j);
                const bool lower = ((tid & j) == 0);
                vv = ((desc == lower) ? (vv > o) : (vv < o)) ? vv : o;
            }
        }
        if (tid < CANDN) cand[tid] = vv;

        for (int k = 64; k <= CANDN; k <<= 1) {
            for (int j = k >> 1; j >= 32; j >>= 1) {
                __syncthreads();
                if (tid < CANDN / 2) {
                    const int t = ((tid & ~(j - 1)) << 1) | (tid & (j - 1));
                    const int p = t | j;
                    const u64 A = cand[t];
                    const u64 B = cand[p];
                    const bool desc = ((t & k) == 0);
                    if (desc ? (A < B) : (A > B)) { cand[t] = B; cand[p] = A; }
                }
            }
            __syncthreads();
            vv = (tid < CANDN) ? cand[tid] : 0ull;
            const bool desc = ((tid & k) == 0);
            #pragma unroll
            for (int j = 16; j >= 1; j >>= 1) {
                const u64 o = __shfl_xor_sync(0xffffffffu, vv, j);
                const bool lower = ((tid & j) == 0);
                vv = ((desc == lower) ? (vv > o) : (vv < o)) ? vv : o;
            }
            if (tid < CANDN) cand[tid] = vv;
        }
        __syncthreads();
    }

    // ---- (d) gather candidate boxes/classes into SMEM ----
    if (tid < cnt) {
        const u64 k  = cand[tid];
        const int a_ = (int)(0xFFFFFFFFu - (u32)k);
        cbox[tid] = g_boxes[(size_t)b * NAP + a_];
        ccls[tid] = g_cls  [(size_t)b * NAP + a_];
    }
    __syncthreads();

    // ---- single-barrier wave walk ----
    int A = 0;                 // committed accepted (visible pre-barrier)
    int T = 0;                 // total accepted so far
    int pbase = 0;             // previous wave base
    u32 pmask = 0;             // previous wave accept mask

    for (int base = 0; base < cnt && T < TOPK; base += 32) {
        const int  c     = base + wid;
        const bool haveC = (c < cnt);
        const int  pb    = (base >> 5) & 1;

        float4 w = make_float4(0.f, 0.f, 0.f, 0.f);
        if (haveC) w = cbox[c];

        bool sA = false;
        if (haveC) {
            for (int a = lane; a < A; a += 32)
                if (iou_gt(w, abox[a])) sA = true;
            if ((pmask >> lane) & 1u)
                if (iou_gt(w, cbox[pbase + lane])) sA = true;
        }
        const bool supA = (__ballot_sync(0xffffffffu, sA) != 0u);

        bool ov = false;
        if (haveC && lane < wid)
            ov = iou_gt(w, cbox[base + lane]);
        const u32 m = __ballot_sync(0xffffffffu, ov);

        if (lane == 0) {
            wv_sup [pb][wid] = (haveC && !supA) ? 0u : 1u;
            wv_mask[pb][wid] = m;
        }
        __syncthreads();

        // fast path: no suppression + no intra-wave overlap (dominant case)
        const u32 sup_l   = wv_sup [pb][lane];
        const u32 mask_l  = wv_mask[pb][lane];
        const u32 supmask = __ballot_sync(0xffffffffu, sup_l != 0u);
        const u32 anyov   = __ballot_sync(0xffffffffu, mask_l != 0u);

        u32 alive;
        int tot;
        if ((supmask | anyov) == 0u) {
            const int take = min(32, TOPK - T);
            alive = (take >= 32) ? 0xffffffffu : ((1u << take) - 1u);
            tot = T + take;
        } else {
            alive = 0u;
            tot = T;
            #pragma unroll
            for (int i = 0; i < 32; i++) {
                if (tot >= TOPK) break;
                if (!wv_sup[pb][i] && ((wv_mask[pb][i] & alive) == 0u)) {
                    alive |= (1u << i);
                    tot++;
                }
            }
        }

        if ((alive >> wid) & 1u) {
            const int slot = T + __popc(alive & ((1u << wid) - 1u));
            if (lane == 0) {
                abox[slot] = w;
                const u64 k = cand[c];
                float* o = out + ((size_t)b * TOPK + slot) * 6;
                o[0] = ccls[c];
                o[1] = __uint_as_float((u32)(k >> 32) ^ 0x80000000u);
                o[2] = w.x; o[3] = w.y; o[4] = w.z; o[5] = w.w;
            }
        }
        A = T;
        pbase = base;
        pmask = alive;
        T = tot;
    }
    __syncthreads();           // all abox writes visible for fallback

    if (tid >= 32) return;     // fallback: warp 0 only (rare)
    int acc = T;

    const float4* gb = g_boxes + (size_t)b * NAP;
    const float*  gc = g_cls   + (size_t)b * NAP;

    if (acc < TOPK) {
        u64 last = pv;
        while (acc < TOPK) {
            u64 best = 0ull;
            for (int j = lane; j < NAP; j += 32) {
                const u64 k = gk[j];
                if (k < last && k > best) best = k;
            }
            const u32 hi = (u32)(best >> 32);
            const u32 mh = __reduce_max_sync(0xffffffffu, hi);
            const u32 lo = (hi == mh) ? (u32)best : 0u;
            const u32 ml = __reduce_max_sync(0xffffffffu, lo);
            if (mh == 0u) break;
            const u64 wkey = ((u64)mh << 32) | (u64)ml;
            const int a_   = (int)(0xFFFFFFFFu - ml);

            float4 w;
            if (lane == 0) w = __ldg(&gb[a_]);
            w.x = __shfl_sync(0xffffffffu, w.x, 0);
            w.y = __shfl_sync(0xffffffffu, w.y, 0);
            w.z = __shfl_sync(0xffffffffu, w.z, 0);
            w.w = __shfl_sync(0xffffffffu, w.w, 0);

            bool sup = false;
            for (int a = lane; a < acc; a += 32)
                if (iou_gt(w, abox[a])) sup = true;
            sup = (__ballot_sync(0xffffffffu, sup) != 0u);

            if (!sup) {
                if (lane == 0) {
                    abox[acc] = w;
                    float* o = out + ((size_t)b * TOPK + acc) * 6;
                    o[0] = __ldg(&gc[a_]);
                    o[1] = __uint_as_float(mh ^ 0x80000000u);
                    o[2] = w.x; o[3] = w.y; o[4] = w.z; o[5] = w.w;
                }
                acc++;
            }
            last = wkey;
            __syncwarp();
        }
    }
}

// ---------------------------------------------------------------------------
extern "C" void kernel_launch(void* const* d_in, const int* in_sizes, int n_in,
                              void* d_out, int out_size)
{
    const float* y   = (const float*)d_in[0];
    float*       out = (float*)d_out;

    const int dec_smem = 64 * NCH * 4;    // 23808 B
    cudaFuncSetAttribute(decode_kernel,
                         cudaFuncAttributeMaxDynamicSharedMemorySize, dec_smem);
    dim3 dgrid((NA + 63) / 64, NB);
    decode_kernel<<<dgrid, 256, dec_smem>>>(y);

    const int nms_smem = SBINS * 4 + CANDN * 8 + CANDN * 16 + CANDN * 4
                       + TOPK * 16;       // 50304 B
    cudaFuncSetAttribute(nms_kernel,
                         cudaFuncAttributeMaxDynamicSharedMemorySize, nms_smem);
    nms_kernel<<<NB, 1024, nms_smem>>>(out);
}